// round 16
// baseline (speedup 1.0000x reference)
#include <cuda_runtime.h>

typedef unsigned long long ull;

// Weights (interleaved transposed) + inter-kernel scratch, all static device.
__device__ float g_WT[2][256 * 64];
__device__ float g_WngT[128 * 64];
__device__ float g_fac[1024 * 5120];  // per block: [f2: mxd1024|m2yd512|mzd1024][f1: same]
__device__ float g_gm[1024 * 4096];   // per block: [cc][rr] gated mean

__global__ void setup_kernel(const float* __restrict__ Wfp1,
                             const float* __restrict__ Wf1,
                             const float* __restrict__ Wng) {
    int tid = blockIdx.x * blockDim.x + threadIdx.x;
    int stride = gridDim.x * blockDim.x;
    for (int i = tid; i < 64 * 256; i += stride) {
        int c = i >> 8, k = i & 255;
        int g = c >> 3, h = (c >> 2) & 1, e = c & 3;
        g_WT[0][k * 64 + h * 32 + g * 4 + e] = Wfp1[i];
        g_WT[1][k * 64 + h * 32 + g * 4 + e] = Wf1[i];
    }
    for (int i = tid; i < 64 * 128; i += stride) {
        int c = i >> 7, k = i & 127;
        int g = c >> 3, h = (c >> 2) & 1, e = c & 3;
        g_WngT[k * 64 + h * 32 + g * 4 + e] = Wng[i];
    }
}

__device__ __forceinline__ float sigmoidf_(float x) {
    return __fdividef(1.0f, 1.0f + __expf(-x));
}
__device__ __forceinline__ float gatef_(float x, float rm) {
    return x * sigmoidf_(fabsf(x - rm));
}
__device__ __forceinline__ float leakyf_(float x) {
    return x > 0.0f ? x : 0.01f * x;
}
__device__ __forceinline__ void ffma2_(ull& d, ull a, ull b) {
    asm("fma.rn.f32x2 %0, %1, %2, %0;" : "+l"(d) : "l"(a), "l"(b));
}
__device__ __forceinline__ ull fmul2_(ull a, ull b) {
    ull r;
    asm("mul.rn.f32x2 %0, %1, %2;" : "=l"(r) : "l"(a), "l"(b));
    return r;
}
__device__ __forceinline__ ull dup2_(float x) {
    ull r;
    unsigned u = __float_as_uint(x);
    asm("mov.b64 %0, {%1, %1};" : "=l"(r) : "r"(u));
    return r;
}
__device__ __forceinline__ float2 unpk_(ull v) {
    float2 r;
    asm("mov.b64 {%0, %1}, %2;" : "=f"(r.x), "=f"(r.y) : "l"(v));
    return r;
}
__device__ __forceinline__ void st_dup2(float* p, float v) {
    *reinterpret_cast<float2*>(p) = make_float2(v, v);
}

__device__ __forceinline__ void copy8(float* __restrict__ dst,
                                      const float* __restrict__ src, int tid) {
    const float4* s = reinterpret_cast<const float4*>(src);
    float4* d = reinterpret_cast<float4*>(dst);
#pragma unroll
    for (int i = 0; i < 8; i++) d[tid + i * 256] = s[tid + i * 256];
}

__device__ __forceinline__ void stage_in(float* __restrict__ sIn,
                                         const float* __restrict__ src,
                                         int row0, int tid) {
    const float4* s =
        reinterpret_cast<const float4*>(src + (size_t)row0 * 64);
#pragma unroll
    for (int it = 0; it < 4; it++) {
        int i = tid + it * 256;
        *reinterpret_cast<float4*>(sIn + (i >> 4) * 68 + (i & 15) * 4) = s[i];
    }
}

// 4-output matvec + sigmoid; input and weights in smem (weights warp-uniform).
__device__ __forceinline__ void mv4s(const float* __restrict__ sIn,
                                     const float* __restrict__ sW16,
                                     const float* __restrict__ b, int rloc,
                                     int q, float h[4]) {
    ull acc[4] = {0, 0, 0, 0};
    const float* xr = sIn + rloc * 68;
#pragma unroll 4
    for (int k = 0; k < 64; k += 4) {
        ulonglong2 xv = *reinterpret_cast<const ulonglong2*>(xr + k);
#pragma unroll
        for (int j = 0; j < 4; j++) {
            ulonglong2 w = *reinterpret_cast<const ulonglong2*>(
                sW16 + (q * 4 + j) * 64 + k);
            ffma2_(acc[j], xv.x, w.x);
            ffma2_(acc[j], xv.y, w.y);
        }
    }
#pragma unroll
    for (int j = 0; j < 4; j++) {
        float2 p = unpk_(acc[j]);
        h[j] = sigmoidf_(p.x + p.y + __ldg(b + q * 4 + j));
    }
}

// ============================================================================
// K1: factor kernel. 64 rows/block, double-buffered staging, 3 CTAs/SM.
// Writes dup'd factor tables (g_fac) and gated mean (g_gm).
// ============================================================================
// smem: sInA 4352 | sInB 4352 | sMvW 6144  = 14848 floats (59.4 KB)
#define K1_SMEM 14848

__global__ void __launch_bounds__(256, 3) k1_factors(
    const float* __restrict__ a, const float* __restrict__ v,
    const float* __restrict__ l, const float* __restrict__ pa,
    const float* __restrict__ pv, const float* __restrict__ pl,
    const float* __restrict__ mean, const float* __restrict__ Wa,
    const float* __restrict__ ba, const float* __restrict__ Wv,
    const float* __restrict__ bv, const float* __restrict__ Wl,
    const float* __restrict__ bl, const float* __restrict__ Wap,
    const float* __restrict__ bap, const float* __restrict__ Wvp,
    const float* __restrict__ bvp, const float* __restrict__ Wlp,
    const float* __restrict__ blp, const float* __restrict__ rm1) {
    extern __shared__ __align__(16) float smem[];
    float* sInA = smem;
    float* sInB = smem + 4352;
    float* sMvW = smem + 8704;

    const int tid = threadIdx.x;
    const int row0 = blockIdx.x * 64;
    const int wid = tid >> 5, lane = tid & 31;
    const int q = lane & 3;
    const int rloc = wid * 8 + (lane >> 2);
    float* fac2 = g_fac + blockIdx.x * 5120;
    float* fac1 = fac2 + 2560;
    float h[4];

    // Stage all 6 matvec weight sets (16x64 each).
    {
        float4* d = reinterpret_cast<float4*>(sMvW);
        d[tid] = reinterpret_cast<const float4*>(Wap)[tid];
        d[256 + tid] = reinterpret_cast<const float4*>(Wvp)[tid];
        d[512 + tid] = reinterpret_cast<const float4*>(Wlp)[tid];
        d[768 + tid] = reinterpret_cast<const float4*>(Wa)[tid];
        d[1024 + tid] = reinterpret_cast<const float4*>(Wv)[tid];
        d[1280 + tid] = reinterpret_cast<const float4*>(Wl)[tid];
    }
    stage_in(sInA, pa, row0, tid);
    __syncthreads();

    stage_in(sInB, pv, row0, tid);
    mv4s(sInA, sMvW, bap, rloc, q, h);
    st_dup2(fac2 + (2 * q) * 128 + 2 * rloc, fmaxf(h[0], h[1]));
    st_dup2(fac2 + (2 * q + 1) * 128 + 2 * rloc, fmaxf(h[2], h[3]));
    __syncthreads();

    stage_in(sInA, pl, row0, tid);
    mv4s(sInB, sMvW + 1024, bvp, rloc, q, h);
    st_dup2(fac2 + 1024 + q * 128 + 2 * rloc,
            fmaxf(fmaxf(h[0], h[1]), fmaxf(h[2], h[3])));
    __syncthreads();

    stage_in(sInB, mean, row0, tid);
    mv4s(sInA, sMvW + 2048, blp, rloc, q, h);
    st_dup2(fac2 + 1536 + (2 * q) * 128 + 2 * rloc, fmaxf(h[0], h[1]));
    st_dup2(fac2 + 1536 + (2 * q + 1) * 128 + 2 * rloc, fmaxf(h[2], h[3]));
    __syncthreads();

    // gated mean from sInB -> g_gm [cc][rr], coalesced writes
    stage_in(sInA, a, row0, tid);
    {
        float* gm = g_gm + blockIdx.x * 4096;
#pragma unroll
        for (int it = 0; it < 16; it++) {
            int i = tid + it * 256;
            int rr = i & 63, cc = i >> 6;
            gm[cc * 64 + rr] = gatef_(sInB[rr * 68 + cc], __ldg(rm1 + 64 + cc));
        }
    }
    __syncthreads();

    stage_in(sInB, v, row0, tid);
    mv4s(sInA, sMvW + 3072, ba, rloc, q, h);
    st_dup2(fac1 + (2 * q) * 128 + 2 * rloc, fmaxf(h[0], h[1]));
    st_dup2(fac1 + (2 * q + 1) * 128 + 2 * rloc, fmaxf(h[2], h[3]));
    __syncthreads();

    stage_in(sInA, l, row0, tid);
    mv4s(sInB, sMvW + 4096, bv, rloc, q, h);
    st_dup2(fac1 + 1024 + q * 128 + 2 * rloc,
            fmaxf(fmaxf(h[0], h[1]), fmaxf(h[2], h[3])));
    __syncthreads();

    mv4s(sInA, sMvW + 5120, bl, rloc, q, h);
    st_dup2(fac1 + 1536 + (2 * q) * 128 + 2 * rloc, fmaxf(h[0], h[1]));
    st_dup2(fac1 + 1536 + (2 * q + 1) * 128 + 2 * rloc, fmaxf(h[2], h[3]));
}

// ============================================================================
// K2: GEMM kernel. R12 inner loops, double-buffered weights, 5 syncs.
// ============================================================================
// Fusion GEMM over one k-half (4 local ix), 2 rows x 8 cols/thread.
__device__ __forceinline__ void gemm_half2(
    const float* __restrict__ sW_, const float* __restrict__ sMxd,
    const float* __restrict__ sM2yd, const float* __restrict__ sMzd, int r0,
    int g, ull acc[2][4]) {
    ull mz2[2][8];
#pragma unroll
    for (int t = 0; t < 8; t++) {
        ulonglong2 m =
            *reinterpret_cast<const ulonglong2*>(sMzd + t * 128 + 2 * r0);
        mz2[0][t] = m.x;
        mz2[1][t] = m.y;
    }
    ull my2[2][4];
#pragma unroll
    for (int iy = 0; iy < 4; iy++) {
        ulonglong2 y =
            *reinterpret_cast<const ulonglong2*>(sM2yd + iy * 128 + 2 * r0);
        my2[0][iy] = y.x;
        my2[1][iy] = y.y;
    }
#pragma unroll 1
    for (int ixl = 0; ixl < 4; ixl++) {
        ulonglong2 ma = *reinterpret_cast<const ulonglong2*>(
            sMxd + ixl * 128 + 2 * r0);  // caller passes sMxd pre-offset
#pragma unroll
        for (int iy = 0; iy < 4; iy++) {
            ull P0 = fmul2_(ma.x, my2[0][iy]);
            ull P1 = fmul2_(ma.y, my2[1][iy]);
            const float* wrow = sW_ + (ixl * 4 + iy) * 512 + g * 4;
#pragma unroll
            for (int t = 0; t < 8; t++) {
                ulonglong2 w0 =
                    *reinterpret_cast<const ulonglong2*>(wrow + t * 64);
                ulonglong2 w1 =
                    *reinterpret_cast<const ulonglong2*>(wrow + t * 64 + 32);
                ull f0 = fmul2_(P0, mz2[0][t]);
                ull f1 = fmul2_(P1, mz2[1][t]);
                ffma2_(acc[0][0], f0, w0.x); ffma2_(acc[0][1], f0, w0.y);
                ffma2_(acc[0][2], f0, w1.x); ffma2_(acc[0][3], f0, w1.y);
                ffma2_(acc[1][0], f1, w0.x); ffma2_(acc[1][1], f1, w0.y);
                ffma2_(acc[1][2], f1, w1.x); ffma2_(acc[1][3], f1, w1.y);
            }
        }
    }
}

// smem: sWa 8192 | sWb 8192 | sGT 8704 ([128k][68]) | sFac 2560
//   sFac: mxd [8][128] @0, m2yd [4][128] @1024, mzd [8][128] @1536
// total 27648 floats = 110592 B -> 2 CTAs/SM
#define K2_WB 8192
#define K2_GT 16384
#define K2_FAC 25088
#define K2_SMEM 27648

__global__ void __launch_bounds__(256, 2) k2_gemm(
    const float* __restrict__ bf1, const float* __restrict__ bfp1,
    const float* __restrict__ bng, const float* __restrict__ rm1,
    const float* __restrict__ rm2, float* __restrict__ out) {
    extern __shared__ __align__(16) float smem[];
    float* sWa = smem;
    float* sWb = smem + K2_WB;
    float* sGT = smem + K2_GT;
    float* sMxd = smem + K2_FAC;
    float* sM2yd = smem + K2_FAC + 1024;
    float* sMzd = smem + K2_FAC + 1536;

    const int tid = threadIdx.x;
    const int row0 = blockIdx.x * 64;
    const int r0 = (tid >> 3) * 2;
    const int g = tid & 7;
    const int c0 = g * 8;
    const float* fac2 = g_fac + blockIdx.x * 5120;
    const float* fac1 = fac2 + 2560;

    // ---- P0: both Wfp1 halves, f2 factors, gated mean -> smem ----
    copy8(sWa, g_WT[0], tid);
    copy8(sWb, g_WT[0] + 8192, tid);
    {
        const float4* s = reinterpret_cast<const float4*>(fac2);
        float4* d = reinterpret_cast<float4*>(sMxd);
#pragma unroll
        for (int i = 0; i < 3; i++) {
            int idx = tid + i * 256;
            if (idx < 640) d[idx] = s[idx];
        }
        const float4* gm =
            reinterpret_cast<const float4*>(g_gm + blockIdx.x * 4096);
#pragma unroll
        for (int it = 0; it < 4; it++) {
            int i = tid + it * 256;   // 1024 float4s: cc = i>>4, rr4 = (i&15)*4
            int cc = i >> 4, rr = (i & 15) * 4;
            *reinterpret_cast<float4*>(sGT + (64 + cc) * 68 + rr) = gm[i];
        }
    }
    __syncthreads();

    // ---- P1: GEMM1 full K (no mid-sync) -> gate -> sGT rows 0..63 ----
    {
        ull acc[2][4] = {};
        gemm_half2(sWa, sMxd, sM2yd, sMzd, r0, g, acc);
        gemm_half2(sWb, sMxd + 4 * 128, sM2yd, sMzd, r0, g, acc);
#pragma unroll
        for (int j = 0; j < 4; j++) {
            int ca = c0 + 2 * j, cb = ca + 1;
            float bca = __ldg(bfp1 + ca), bcb = __ldg(bfp1 + cb);
            float rca = __ldg(rm1 + ca), rcb = __ldg(rm1 + cb);
            float2 p0 = unpk_(acc[0][j]);
            float2 p1 = unpk_(acc[1][j]);
            *reinterpret_cast<float2*>(sGT + ca * 68 + r0) =
                make_float2(gatef_(leakyf_(p0.x + bca), rca),
                            gatef_(leakyf_(p1.x + bca), rca));
            *reinterpret_cast<float2*>(sGT + cb * 68 + r0) =
                make_float2(gatef_(leakyf_(p0.y + bcb), rcb),
                            gatef_(leakyf_(p1.y + bcb), rcb));
        }
    }
    __syncthreads();

    // ---- P2: WngT -> sWa; f1 factors -> sFac ----
    copy8(sWa, g_WngT, tid);
    {
        const float4* s = reinterpret_cast<const float4*>(fac1);
        float4* d = reinterpret_cast<float4*>(sMxd);
#pragma unroll
        for (int i = 0; i < 3; i++) {
            int idx = tid + i * 256;
            if (idx < 640) d[idx] = s[idx];
        }
    }
    __syncthreads();

    // ---- P3: Wf1 half0 -> sWb (overlapped); GEMM2 -> out[:,0:64] ----
    copy8(sWb, g_WT[1], tid);
    {
        ull acc2[2][4] = {};
#pragma unroll 4
        for (int k = 0; k < 128; k++) {
            ull fp = *reinterpret_cast<const ull*>(sGT + k * 68 + r0);
            float2 fv = unpk_(fp);
            ull f0 = dup2_(fv.x), f1 = dup2_(fv.y);
            const float* wr = sWa + k * 64 + g * 4;
            ulonglong2 w0 = *reinterpret_cast<const ulonglong2*>(wr);
            ulonglong2 w1 = *reinterpret_cast<const ulonglong2*>(wr + 32);
            ffma2_(acc2[0][0], f0, w0.x); ffma2_(acc2[0][1], f0, w0.y);
            ffma2_(acc2[0][2], f0, w1.x); ffma2_(acc2[0][3], f0, w1.y);
            ffma2_(acc2[1][0], f1, w0.x); ffma2_(acc2[1][1], f1, w0.y);
            ffma2_(acc2[1][2], f1, w1.x); ffma2_(acc2[1][3], f1, w1.y);
        }
        float4 bbA = __ldg(reinterpret_cast<const float4*>(bng + c0));
        float4 bbB = __ldg(reinterpret_cast<const float4*>(bng + c0 + 4));
        float4 rmA = __ldg(reinterpret_cast<const float4*>(rm2 + c0));
        float4 rmB = __ldg(reinterpret_cast<const float4*>(rm2 + c0 + 4));
#pragma unroll
        for (int i = 0; i < 2; i++) {
            float2 p0 = unpk_(acc2[i][0]), p1 = unpk_(acc2[i][1]);
            float2 p2 = unpk_(acc2[i][2]), p3 = unpk_(acc2[i][3]);
            float* orow = out + (row0 + r0 + i) * 128 + c0;
            *reinterpret_cast<float4*>(orow) =
                make_float4(gatef_(p0.x + bbA.x, rmA.x),
                            gatef_(p0.y + bbA.y, rmA.y),
                            gatef_(p1.x + bbA.z, rmA.z),
                            gatef_(p1.y + bbA.w, rmA.w));
            *reinterpret_cast<float4*>(orow + 4) =
                make_float4(gatef_(p2.x + bbB.x, rmB.x),
                            gatef_(p2.y + bbB.y, rmB.y),
                            gatef_(p3.x + bbB.z, rmB.z),
                            gatef_(p3.y + bbB.w, rmB.w));
        }
    }
    __syncthreads();

    // ---- P4: Wf1 half1 -> sWa (overlapped with GEMM3 half0 on sWb) ----
    ull acc[2][4] = {};
    copy8(sWa, g_WT[1] + 8192, tid);
    gemm_half2(sWb, sMxd, sM2yd, sMzd, r0, g, acc);
    __syncthreads();

    // ---- P5: GEMM3 half1 -> out[:,64:128] ----
    {
        gemm_half2(sWa, sMxd + 4 * 128, sM2yd, sMzd, r0, g, acc);
        float4 bbA = __ldg(reinterpret_cast<const float4*>(bf1 + c0));
        float4 bbB = __ldg(reinterpret_cast<const float4*>(bf1 + c0 + 4));
        float4 rmA = __ldg(reinterpret_cast<const float4*>(rm2 + 64 + c0));
        float4 rmB = __ldg(reinterpret_cast<const float4*>(rm2 + 64 + c0 + 4));
#pragma unroll
        for (int i = 0; i < 2; i++) {
            float2 p0 = unpk_(acc[i][0]), p1 = unpk_(acc[i][1]);
            float2 p2 = unpk_(acc[i][2]), p3 = unpk_(acc[i][3]);
            float* orow = out + (row0 + r0 + i) * 128 + 64 + c0;
            *reinterpret_cast<float4*>(orow) =
                make_float4(gatef_(leakyf_(p0.x + bbA.x), rmA.x),
                            gatef_(leakyf_(p0.y + bbA.y), rmA.y),
                            gatef_(leakyf_(p1.x + bbA.z), rmA.z),
                            gatef_(leakyf_(p1.y + bbA.w), rmA.w));
            *reinterpret_cast<float4*>(orow + 4) =
                make_float4(gatef_(leakyf_(p2.x + bbB.x), rmB.x),
                            gatef_(leakyf_(p2.y + bbB.y), rmB.y),
                            gatef_(leakyf_(p3.x + bbB.z), rmB.z),
                            gatef_(leakyf_(p3.y + bbB.w), rmB.w));
        }
    }
}

extern "C" void kernel_launch(void* const* d_in, const int* in_sizes, int n_in,
                              void* d_out, int out_size) {
    const float* a    = (const float*)d_in[0];
    const float* v    = (const float*)d_in[1];
    const float* l    = (const float*)d_in[2];
    const float* pa   = (const float*)d_in[3];
    const float* pv   = (const float*)d_in[4];
    const float* pl   = (const float*)d_in[5];
    const float* mean = (const float*)d_in[6];
    const float* Wa   = (const float*)d_in[7];
    const float* ba   = (const float*)d_in[8];
    const float* Wv   = (const float*)d_in[9];
    const float* bv   = (const float*)d_in[10];
    const float* Wl   = (const float*)d_in[11];
    const float* bl   = (const float*)d_in[12];
    const float* Wap  = (const float*)d_in[13];
    const float* bap  = (const float*)d_in[14];
    const float* Wvp  = (const float*)d_in[15];
    const float* bvp  = (const float*)d_in[16];
    const float* Wlp  = (const float*)d_in[17];
    const float* blp  = (const float*)d_in[18];
    const float* Wf1  = (const float*)d_in[19];
    const float* bf1  = (const float*)d_in[20];
    const float* Wfp1 = (const float*)d_in[21];
    const float* bfp1 = (const float*)d_in[22];
    const float* Wng  = (const float*)d_in[23];
    const float* bng  = (const float*)d_in[24];
    const float* rm1  = (const float*)d_in[25];
    const float* rm2  = (const float*)d_in[26];

    int nrows = in_sizes[0] / 64;
    int nblk = nrows / 64;
    static int smem_set = 0;
    if (!smem_set) {
        cudaFuncSetAttribute(k1_factors,
                             cudaFuncAttributeMaxDynamicSharedMemorySize,
                             K1_SMEM * 4);
        cudaFuncSetAttribute(k2_gemm,
                             cudaFuncAttributeMaxDynamicSharedMemorySize,
                             K2_SMEM * 4);
        smem_set = 1;
    }

    setup_kernel<<<64, 256>>>(Wfp1, Wf1, Wng);
    k1_factors<<<nblk, 256, K1_SMEM * 4>>>(
        a, v, l, pa, pv, pl, mean, Wa, ba, Wv, bv, Wl, bl, Wap, bap, Wvp, bvp,
        Wlp, blp, rm1);
    k2_gemm<<<nblk, 256, K2_SMEM * 4>>>(bf1, bfp1, bng, rm1, rm2,
                                        (float*)d_out);
}

// round 17
// speedup vs baseline: 1.0061x; 1.0061x over previous
#include <cuda_runtime.h>

typedef unsigned long long ull;

// Weights in global, built per replay by setup_kernel.
// Interleaved transposed layout (fusion weights AND WngT):
//   d = k*64 + h*32 + g*4 + e  <->  c = g*8 + h*4 + e   (h<2, e<4, g<8)
__device__ float g_WT[2][256 * 64];
__device__ float g_WngT[128 * 64];

__global__ void setup_kernel(const float* __restrict__ Wfp1,
                             const float* __restrict__ Wf1,
                             const float* __restrict__ Wng) {
    int tid = blockIdx.x * blockDim.x + threadIdx.x;
    int stride = gridDim.x * blockDim.x;
    for (int i = tid; i < 64 * 256; i += stride) {
        int c = i >> 8, k = i & 255;
        int g = c >> 3, h = (c >> 2) & 1, e = c & 3;
        g_WT[0][k * 64 + h * 32 + g * 4 + e] = Wfp1[i];
        g_WT[1][k * 64 + h * 32 + g * 4 + e] = Wf1[i];
    }
    for (int i = tid; i < 64 * 128; i += stride) {
        int c = i >> 7, k = i & 127;
        int g = c >> 3, h = (c >> 2) & 1, e = c & 3;
        g_WngT[k * 64 + h * 32 + g * 4 + e] = Wng[i];
    }
}

__device__ __forceinline__ float sigmoidf_(float x) {
    return __fdividef(1.0f, 1.0f + __expf(-x));
}
__device__ __forceinline__ float gatef_(float x, float rm) {
    return x * sigmoidf_(fabsf(x - rm));
}
__device__ __forceinline__ float leakyf_(float x) {
    return x > 0.0f ? x : 0.01f * x;
}
__device__ __forceinline__ void ffma2_(ull& d, ull a, ull b) {
    asm("fma.rn.f32x2 %0, %1, %2, %0;" : "+l"(d) : "l"(a), "l"(b));
}
__device__ __forceinline__ ull fmul2_(ull a, ull b) {
    ull r;
    asm("mul.rn.f32x2 %0, %1, %2;" : "=l"(r) : "l"(a), "l"(b));
    return r;
}
__device__ __forceinline__ ull dup2_(float x) {
    ull r;
    unsigned u = __float_as_uint(x);
    asm("mov.b64 %0, {%1, %1};" : "=l"(r) : "r"(u));
    return r;
}
__device__ __forceinline__ float2 unpk_(ull v) {
    float2 r;
    asm("mov.b64 {%0, %1}, %2;" : "=f"(r.x), "=f"(r.y) : "l"(v));
    return r;
}
__device__ __forceinline__ void st_dup2(float* p, float v) {
    *reinterpret_cast<float2*>(p) = make_float2(v, v);
}

// Copy 8192 floats global -> smem, coalesced.
__device__ __forceinline__ void copy8(float* __restrict__ dst,
                                      const float* __restrict__ src, int tid) {
    const float4* s = reinterpret_cast<const float4*>(src);
    float4* d = reinterpret_cast<float4*>(dst);
#pragma unroll
    for (int i = 0; i < 8; i++) d[tid + i * 256] = s[tid + i * 256];
}
// Copy 4096 floats global -> smem, coalesced.
__device__ __forceinline__ void copy4(float* __restrict__ dst,
                                      const float* __restrict__ src, int tid) {
    const float4* s = reinterpret_cast<const float4*>(src);
    float4* d = reinterpret_cast<float4*>(dst);
#pragma unroll
    for (int i = 0; i < 4; i++) d[tid + i * 256] = s[tid + i * 256];
}

// Stage three matvec weight sets (16x64 each) into sX[3][1024].
__device__ __forceinline__ void stage_mvw(float* __restrict__ sX,
                                          const float* __restrict__ Wx,
                                          const float* __restrict__ Wy,
                                          const float* __restrict__ Wz,
                                          int tid) {
    float4* d = reinterpret_cast<float4*>(sX);
    d[tid] = reinterpret_cast<const float4*>(Wx)[tid];
    d[256 + tid] = reinterpret_cast<const float4*>(Wy)[tid];
    d[512 + tid] = reinterpret_cast<const float4*>(Wz)[tid];
}

// Stage one modality (64 rows x 64 floats) into buf[64][68], coalesced.
__device__ __forceinline__ void stage_in(float* __restrict__ buf,
                                         const float* __restrict__ src,
                                         int row0, int tid) {
    const float4* s =
        reinterpret_cast<const float4*>(src + (size_t)row0 * 64);
#pragma unroll
    for (int it = 0; it < 4; it++) {
        int i = tid + it * 256;
        *reinterpret_cast<float4*>(buf + (i >> 4) * 68 + (i & 15) * 4) = s[i];
    }
}

// 4-output matvec + sigmoid; input and weights both in smem.
// q = lane&3 selects output quad; rloc = wid*8 + (lane>>2).
__device__ __forceinline__ void mv4s(const float* __restrict__ sInb,
                                     const float* __restrict__ sW16,
                                     const float* __restrict__ b, int rloc,
                                     int q, float h[4]) {
    ull acc[4] = {0, 0, 0, 0};
    const float* xr = sInb + rloc * 68;
#pragma unroll 4
    for (int k = 0; k < 64; k += 4) {
        ulonglong2 xv = *reinterpret_cast<const ulonglong2*>(xr + k);
#pragma unroll
        for (int j = 0; j < 4; j++) {
            ulonglong2 w = *reinterpret_cast<const ulonglong2*>(
                sW16 + (q * 4 + j) * 64 + k);
            ffma2_(acc[j], xv.x, w.x);
            ffma2_(acc[j], xv.y, w.y);
        }
    }
#pragma unroll
    for (int j = 0; j < 4; j++) {
        float2 p = unpk_(acc[j]);
        h[j] = sigmoidf_(p.x + p.y + __ldg(b + q * 4 + j));
    }
}

// Load mz / m2y factor tables (dup'd) into registers once per GEMM.
__device__ __forceinline__ void load_fac(const float* __restrict__ sMzd,
                                         const float* __restrict__ sM2yd,
                                         int r0, ull mz2[2][8],
                                         ull my2[2][4]) {
#pragma unroll
    for (int t = 0; t < 8; t++) {
        ulonglong2 m =
            *reinterpret_cast<const ulonglong2*>(sMzd + t * 128 + 2 * r0);
        mz2[0][t] = m.x;
        mz2[1][t] = m.y;
    }
#pragma unroll
    for (int iy = 0; iy < 4; iy++) {
        ulonglong2 y =
            *reinterpret_cast<const ulonglong2*>(sM2yd + iy * 128 + 2 * r0);
        my2[0][iy] = y.x;
        my2[1][iy] = y.y;
    }
}

// Fusion GEMM quarter: 2 ix groups (K=64), 2 rows x 8 cols/thread.
// sW4 = 4096-float weight quarter; gix0 = global ix base of the quarter.
__device__ __forceinline__ void gemm_q2(
    const float* __restrict__ sW4, const float* __restrict__ sMxd, int gix0,
    int r0, int g, const ull mz2[2][8], const ull my2[2][4], ull acc[2][4]) {
#pragma unroll
    for (int ixl = 0; ixl < 2; ixl++) {
        ulonglong2 ma = *reinterpret_cast<const ulonglong2*>(
            sMxd + (gix0 + ixl) * 128 + 2 * r0);
#pragma unroll
        for (int iy = 0; iy < 4; iy++) {
            ull P0 = fmul2_(ma.x, my2[0][iy]);
            ull P1 = fmul2_(ma.y, my2[1][iy]);
            const float* wrow = sW4 + (ixl * 4 + iy) * 512 + g * 4;
#pragma unroll
            for (int t = 0; t < 8; t++) {
                ulonglong2 w0 =
                    *reinterpret_cast<const ulonglong2*>(wrow + t * 64);
                ulonglong2 w1 =
                    *reinterpret_cast<const ulonglong2*>(wrow + t * 64 + 32);
                ull f0 = fmul2_(P0, mz2[0][t]);
                ull f1 = fmul2_(P1, mz2[1][t]);
                ffma2_(acc[0][0], f0, w0.x); ffma2_(acc[0][1], f0, w0.y);
                ffma2_(acc[0][2], f0, w1.x); ffma2_(acc[0][3], f0, w1.y);
                ffma2_(acc[1][0], f1, w0.x); ffma2_(acc[1][1], f1, w0.y);
                ffma2_(acc[1][2], f1, w1.x); ffma2_(acc[1][3], f1, w1.y);
            }
        }
    }
}

// Shared layout (floats):
//  sW    @ 0     : 8192   (two 4096 weight quarters)
//  sGT   @ 8192  : 8704   ([128 k][68]; low 4096/4352 doubles as Q2 buf / pv)
//  sMxd  @ 16896 : 1024   ([8][128] dup'd)
//  sM2yd @ 17920 : 512    ([4][128])
//  sMzd  @ 18432 : 1024   ([8][128])
//  sIn   @ 19456 : 4352   ([64][68] staged inputs; first 4096 = Wf1 Q0 buf)
//  sX    @ 23808 : 4096   (matvec weights 3072 / Wf1 Q1 buf)
//  total 27904 floats = 111616 B -> 2 CTAs/SM
#define OFF_GT 8192
#define OFF_MXD 16896
#define OFF_M2YD 17920
#define OFF_MZD 18432
#define OFF_IN 19456
#define OFF_X 23808
#define SMEM_FLOATS 27904

__global__ void __launch_bounds__(256, 2) fusion_main(
    const float* __restrict__ a, const float* __restrict__ v,
    const float* __restrict__ l, const float* __restrict__ pa,
    const float* __restrict__ pv, const float* __restrict__ pl,
    const float* __restrict__ mean, const float* __restrict__ Wa,
    const float* __restrict__ ba, const float* __restrict__ Wv,
    const float* __restrict__ bv, const float* __restrict__ Wl,
    const float* __restrict__ bl, const float* __restrict__ Wap,
    const float* __restrict__ bap, const float* __restrict__ Wvp,
    const float* __restrict__ bvp, const float* __restrict__ Wlp,
    const float* __restrict__ blp, const float* __restrict__ bf1,
    const float* __restrict__ bfp1, const float* __restrict__ bng,
    const float* __restrict__ rm1, const float* __restrict__ rm2,
    float* __restrict__ out) {
    extern __shared__ __align__(16) float smem[];
    float* sW_ = smem;
    float* sGT = smem + OFF_GT;
    float* sMxd = smem + OFF_MXD;
    float* sM2yd = smem + OFF_M2YD;
    float* sMzd = smem + OFF_MZD;
    float* sIn = smem + OFF_IN;
    float* sX = smem + OFF_X;

    const int tid = threadIdx.x;
    const int row0 = blockIdx.x * 64;
    const int wid = tid >> 5, lane = tid & 31;
    const int q = lane & 3;                  // matvec output quad
    const int rloc = wid * 8 + (lane >> 2);  // matvec row
    const int r0 = (tid >> 3) * 2;           // GEMM rows (2 per thread)
    const int g = tid & 7;                   // GEMM col group
    const int c0 = g * 8;
    float h[4];

    // ---- P0: Wfp1 Q0+Q1 -> sW; mvW -> sX; gated mean -> sGT-hi;
    //          pa -> sIn, pv -> sGT-low ----
    copy8(sW_, g_WT[0], tid);
    stage_mvw(sX, Wap, Wvp, Wlp, tid);
#pragma unroll
    for (int it = 0; it < 16; it++) {
        int i = tid + it * 256;
        int rr = i >> 6, cc = i & 63;
        sGT[(64 + cc) * 68 + rr] =
            gatef_(__ldg(mean + (row0 + rr) * 64 + cc), __ldg(rm1 + 64 + cc));
    }
    stage_in(sIn, pa, row0, tid);
    stage_in(sGT, pv, row0, tid);  // sGT-low: dead until GEMM1 Q2
    __syncthreads();
    mv4s(sIn, sX, bap, rloc, q, h);
    st_dup2(sMxd + (2 * q) * 128 + 2 * rloc, fmaxf(h[0], h[1]));
    st_dup2(sMxd + (2 * q + 1) * 128 + 2 * rloc, fmaxf(h[2], h[3]));
    mv4s(sGT, sX + 1024, bvp, rloc, q, h);
    st_dup2(sM2yd + q * 128 + 2 * rloc,
            fmaxf(fmaxf(h[0], h[1]), fmaxf(h[2], h[3])));
    __syncthreads();
    stage_in(sIn, pl, row0, tid);
    __syncthreads();
    mv4s(sIn, sX + 2048, blp, rloc, q, h);
    st_dup2(sMzd + (2 * q) * 128 + 2 * rloc, fmaxf(h[0], h[1]));
    st_dup2(sMzd + (2 * q + 1) * 128 + 2 * rloc, fmaxf(h[2], h[3]));
    __syncthreads();

    // ---- P1: GEMM1, quarters pipelined -> gate -> sGT rows 0..63 ----
    {
        ull acc[2][4] = {};
        ull mz2[2][8], my2[2][4];
        load_fac(sMzd, sM2yd, r0, mz2, my2);
        copy4(sGT, g_WT[0] + 8192, tid);  // Q2 -> sGT-low (hidden)
        gemm_q2(sW_, sMxd, 0, r0, g, mz2, my2, acc);
        gemm_q2(sW_ + 4096, sMxd, 2, r0, g, mz2, my2, acc);
        __syncthreads();
        copy4(sW_, g_WT[0] + 12288, tid);  // Q3 -> sW-low (hidden)
        gemm_q2(sGT, sMxd, 4, r0, g, mz2, my2, acc);
        __syncthreads();
        gemm_q2(sW_, sMxd, 6, r0, g, mz2, my2, acc);
#pragma unroll
        for (int j = 0; j < 4; j++) {
            int ca = c0 + 2 * j, cb = ca + 1;
            float bca = __ldg(bfp1 + ca), bcb = __ldg(bfp1 + cb);
            float rca = __ldg(rm1 + ca), rcb = __ldg(rm1 + cb);
            float2 p0 = unpk_(acc[0][j]);
            float2 p1 = unpk_(acc[1][j]);
            *reinterpret_cast<float2*>(sGT + ca * 68 + r0) =
                make_float2(gatef_(leakyf_(p0.x + bca), rca),
                            gatef_(leakyf_(p1.x + bca), rca));
            *reinterpret_cast<float2*>(sGT + cb * 68 + r0) =
                make_float2(gatef_(leakyf_(p0.y + bcb), rcb),
                            gatef_(leakyf_(p1.y + bcb), rcb));
        }
        __syncthreads();
    }

    // ---- P2: WngT -> sW; mvW(branch1) -> sX; fusion-1 factors ----
    copy8(sW_, g_WngT, tid);
    stage_mvw(sX, Wa, Wv, Wl, tid);
    stage_in(sIn, a, row0, tid);
    __syncthreads();
    mv4s(sIn, sX, ba, rloc, q, h);
    st_dup2(sMxd + (2 * q) * 128 + 2 * rloc, fmaxf(h[0], h[1]));
    st_dup2(sMxd + (2 * q + 1) * 128 + 2 * rloc, fmaxf(h[2], h[3]));
    __syncthreads();
    stage_in(sIn, v, row0, tid);
    __syncthreads();
    mv4s(sIn, sX + 1024, bv, rloc, q, h);
    st_dup2(sM2yd + q * 128 + 2 * rloc,
            fmaxf(fmaxf(h[0], h[1]), fmaxf(h[2], h[3])));
    __syncthreads();
    stage_in(sIn, l, row0, tid);
    __syncthreads();
    mv4s(sIn, sX + 2048, bl, rloc, q, h);
    st_dup2(sMzd + (2 * q) * 128 + 2 * rloc, fmaxf(h[0], h[1]));
    st_dup2(sMzd + (2 * q + 1) * 128 + 2 * rloc, fmaxf(h[2], h[3]));
    __syncthreads();

    // ---- P3: GEMM2 (K=128, 2r x 8c); Wf1 Q0/Q1 preloads hidden ----
    {
        copy4(sIn, g_WT[1], tid);        // Wf1 Q0 (sIn dead)
        copy4(sX, g_WT[1] + 4096, tid);  // Wf1 Q1 (sX dead)
        ull acc2[2][4] = {};
#pragma unroll 4
        for (int k = 0; k < 128; k++) {
            ull fp = *reinterpret_cast<const ull*>(sGT + k * 68 + r0);
            float2 fv = unpk_(fp);
            ull f0 = dup2_(fv.x), f1 = dup2_(fv.y);
            const float* wr = sW_ + k * 64 + g * 4;
            ulonglong2 w0 = *reinterpret_cast<const ulonglong2*>(wr);
            ulonglong2 w1 = *reinterpret_cast<const ulonglong2*>(wr + 32);
            ffma2_(acc2[0][0], f0, w0.x); ffma2_(acc2[0][1], f0, w0.y);
            ffma2_(acc2[0][2], f0, w1.x); ffma2_(acc2[0][3], f0, w1.y);
            ffma2_(acc2[1][0], f1, w0.x); ffma2_(acc2[1][1], f1, w0.y);
            ffma2_(acc2[1][2], f1, w1.x); ffma2_(acc2[1][3], f1, w1.y);
        }
        float4 bbA = __ldg(reinterpret_cast<const float4*>(bng + c0));
        float4 bbB = __ldg(reinterpret_cast<const float4*>(bng + c0 + 4));
        float4 rmA = __ldg(reinterpret_cast<const float4*>(rm2 + c0));
        float4 rmB = __ldg(reinterpret_cast<const float4*>(rm2 + c0 + 4));
#pragma unroll
        for (int i = 0; i < 2; i++) {
            float2 p0 = unpk_(acc2[i][0]), p1 = unpk_(acc2[i][1]);
            float2 p2 = unpk_(acc2[i][2]), p3 = unpk_(acc2[i][3]);
            float* orow = out + (row0 + r0 + i) * 128 + c0;
            *reinterpret_cast<float4*>(orow) =
                make_float4(gatef_(p0.x + bbA.x, rmA.x),
                            gatef_(p0.y + bbA.y, rmA.y),
                            gatef_(p1.x + bbA.z, rmA.z),
                            gatef_(p1.y + bbA.w, rmA.w));
            *reinterpret_cast<float4*>(orow + 4) =
                make_float4(gatef_(p2.x + bbB.x, rmB.x),
                            gatef_(p2.y + bbB.y, rmB.y),
                            gatef_(p3.x + bbB.z, rmB.z),
                            gatef_(p3.y + bbB.w, rmB.w));
        }
        __syncthreads();
    }

    // ---- P4: GEMM3, quarters pipelined -> out[:,64:128] ----
    {
        ull acc[2][4] = {};
        ull mz2[2][8], my2[2][4];
        load_fac(sMzd, sM2yd, r0, mz2, my2);
        copy8(sW_, g_WT[1] + 8192, tid);  // Q2+Q3 -> sW (hidden)
        gemm_q2(sIn, sMxd, 0, r0, g, mz2, my2, acc);
        gemm_q2(sX, sMxd, 2, r0, g, mz2, my2, acc);
        __syncthreads();
        gemm_q2(sW_, sMxd, 4, r0, g, mz2, my2, acc);
        gemm_q2(sW_ + 4096, sMxd, 6, r0, g, mz2, my2, acc);
        float4 bbA = __ldg(reinterpret_cast<const float4*>(bf1 + c0));
        float4 bbB = __ldg(reinterpret_cast<const float4*>(bf1 + c0 + 4));
        float4 rmA = __ldg(reinterpret_cast<const float4*>(rm2 + 64 + c0));
        float4 rmB = __ldg(reinterpret_cast<const float4*>(rm2 + 64 + c0 + 4));
#pragma unroll
        for (int i = 0; i < 2; i++) {
            float2 p0 = unpk_(acc[i][0]), p1 = unpk_(acc[i][1]);
            float2 p2 = unpk_(acc[i][2]), p3 = unpk_(acc[i][3]);
            float* orow = out + (row0 + r0 + i) * 128 + 64 + c0;
            *reinterpret_cast<float4*>(orow) =
                make_float4(gatef_(leakyf_(p0.x + bbA.x), rmA.x),
                            gatef_(leakyf_(p0.y + bbA.y), rmA.y),
                            gatef_(leakyf_(p1.x + bbA.z), rmA.z),
                            gatef_(leakyf_(p1.y + bbA.w), rmA.w));
            *reinterpret_cast<float4*>(orow + 4) =
                make_float4(gatef_(leakyf_(p2.x + bbB.x), rmB.x),
                            gatef_(leakyf_(p2.y + bbB.y), rmB.y),
                            gatef_(leakyf_(p3.x + bbB.z), rmB.z),
                            gatef_(leakyf_(p3.y + bbB.w), rmB.w));
        }
    }
}

extern "C" void kernel_launch(void* const* d_in, const int* in_sizes, int n_in,
                              void* d_out, int out_size) {
    const float* a    = (const float*)d_in[0];
    const float* v    = (const float*)d_in[1];
    const float* l    = (const float*)d_in[2];
    const float* pa   = (const float*)d_in[3];
    const float* pv   = (const float*)d_in[4];
    const float* pl   = (const float*)d_in[5];
    const float* mean = (const float*)d_in[6];
    const float* Wa   = (const float*)d_in[7];
    const float* ba   = (const float*)d_in[8];
    const float* Wv   = (const float*)d_in[9];
    const float* bv   = (const float*)d_in[10];
    const float* Wl   = (const float*)d_in[11];
    const float* bl   = (const float*)d_in[12];
    const float* Wap  = (const float*)d_in[13];
    const float* bap  = (const float*)d_in[14];
    const float* Wvp  = (const float*)d_in[15];
    const float* bvp  = (const float*)d_in[16];
    const float* Wlp  = (const float*)d_in[17];
    const float* blp  = (const float*)d_in[18];
    const float* Wf1  = (const float*)d_in[19];
    const float* bf1  = (const float*)d_in[20];
    const float* Wfp1 = (const float*)d_in[21];
    const float* bfp1 = (const float*)d_in[22];
    const float* Wng  = (const float*)d_in[23];
    const float* bng  = (const float*)d_in[24];
    const float* rm1  = (const float*)d_in[25];
    const float* rm2  = (const float*)d_in[26];

    int nrows = in_sizes[0] / 64;
    static int smem_set = 0;
    if (!smem_set) {
        cudaFuncSetAttribute(fusion_main,
                             cudaFuncAttributeMaxDynamicSharedMemorySize,
                             SMEM_FLOATS * 4);
        smem_set = 1;
    }

    setup_kernel<<<64, 256>>>(Wfp1, Wf1, Wng);
    fusion_main<<<nrows / 64, 256, SMEM_FLOATS * 4>>>(
        a, v, l, pa, pv, pl, mean, Wa, ba, Wv, bv, Wl, bl, Wap, bap, Wvp, bvp,
        Wlp, blp, bf1, bfp1, bng, rm1, rm2, (float*)d_out);
}